// round 10
// baseline (speedup 1.0000x reference)
#include <cuda_runtime.h>
#include <cuda_fp16.h>
#include <math.h>
#include <stdint.h>

#define N_TOK 4096
#define DIMD  1024
#define HID   4096
#define OUTD  1024
#define NE    8
#define RMAX  (2*N_TOK)

#define NRT   24                      // row-tile bound per expert (3072 rows; mean 1024)
#define NG1   (NE*NRT*16)             // 3072 G1 items
#define NG2   (NE*NRT*4)              // 768  G2 items
#define NTOT  (NG1+NG2)
#define CONV2_BLOCKS 8192

// ---------------- scratch (static device globals) ----------------
__device__ __half g_xh[(size_t)N_TOK * DIMD];      //  8 MB x fp16 (token order)
__device__ __half g_hh[(size_t)RMAX * HID];        // 64 MB GEMM1 out (fp16, expert-sorted)
__device__ float  g_ybuf[(size_t)RMAX * OUTD];     // 32 MB GEMM2 out
__device__ __half g_w1h[(size_t)NE * DIMD * HID];  // 64 MB
__device__ __half g_w2h[(size_t)NE * HID * OUTD];  // 64 MB
__device__ int   g_perm[RMAX];
__device__ float g_wgt[RMAX];
__device__ int   g_rowpos[N_TOK * 2];
__device__ int   g_sel[N_TOK * 2];
__device__ float g_w[N_TOK * 2];
__device__ int   g_cnt[NE];
__device__ int   g_off[NE];
__device__ int   g_qhead;
__device__ int   g_done1[NE];
__device__ int   g_w2ready;

// ---------------- helpers ----------------
__device__ __forceinline__ void cp16(void* dst, const void* src) {
    unsigned sd = (unsigned)__cvta_generic_to_shared(dst);
    asm volatile("cp.async.cg.shared.global [%0], [%1], 16;" :: "r"(sd), "l"(src));
}
__device__ __forceinline__ uint32_t smem_u32(const void* p) {
    uint32_t a;
    asm("{ .reg .u64 t; cvta.to.shared.u64 t, %1; cvt.u32.u64 %0, t; }" : "=r"(a) : "l"(p));
    return a;
}
__device__ __forceinline__ void ldm4(uint32_t r[4], uint32_t addr) {
    asm volatile("ldmatrix.sync.aligned.m8n8.x4.shared.b16 {%0,%1,%2,%3}, [%4];"
        : "=r"(r[0]), "=r"(r[1]), "=r"(r[2]), "=r"(r[3]) : "r"(addr));
}
__device__ __forceinline__ void ldm4t(uint32_t r[4], uint32_t addr) {
    asm volatile("ldmatrix.sync.aligned.m8n8.x4.trans.shared.b16 {%0,%1,%2,%3}, [%4];"
        : "=r"(r[0]), "=r"(r[1]), "=r"(r[2]), "=r"(r[3]) : "r"(addr));
}
__device__ __forceinline__ void mma16816(float c[4], const uint32_t a[4], const uint32_t* b) {
    asm volatile("mma.sync.aligned.m16n8k16.row.col.f32.f16.f16.f32 "
        "{%0,%1,%2,%3}, {%4,%5,%6,%7}, {%8,%9}, {%0,%1,%2,%3};"
        : "+f"(c[0]), "+f"(c[1]), "+f"(c[2]), "+f"(c[3])
        : "r"(a[0]), "r"(a[1]), "r"(a[2]), "r"(a[3]), "r"(b[0]), "r"(b[1]));
}

#define SW128(x) ((x) ^ (((x) >> 3) & 0x70))
#define STAGE   49152
#define SMEM_TOTAL (4 * STAGE)

// ---------------- flags init (before fork; resets per replay) ----------------
__global__ void flags_init_kernel() {
    int t = threadIdx.x;
    if (t == 0) { g_qhead = 0; g_w2ready = 0; }
    if (t < NE) g_done1[t] = 0;
}

// ---------------- fused gate + x->fp16: warp per token ----------------
__global__ void gate_kernel(const float* __restrict__ x, const float* __restrict__ Wg) {
    const int wid  = threadIdx.x >> 5, lane = threadIdx.x & 31;
    const int n    = blockIdx.x * 8 + wid;
    const float* xr = x + (size_t)n * DIMD;
    __half2* xhr = (__half2*)(g_xh + (size_t)n * DIMD);

    float acc[NE];
#pragma unroll
    for (int e = 0; e < NE; e++) acc[e] = 0.f;
#pragma unroll 4
    for (int i = 0; i < DIMD / 64; i++) {
        int d = 64 * i + 2 * lane;
        float2 xv = *(const float2*)(xr + d);
        xhr[d >> 1] = __floats2half2_rn(xv.x, xv.y);
        const float4* wr0 = (const float4*)(Wg + (size_t)d * NE);
        const float4* wr1 = (const float4*)(Wg + (size_t)(d + 1) * NE);
        float4 a0 = wr0[0], a1 = wr0[1], b0 = wr1[0], b1 = wr1[1];
        acc[0] += xv.x * a0.x + xv.y * b0.x;
        acc[1] += xv.x * a0.y + xv.y * b0.y;
        acc[2] += xv.x * a0.z + xv.y * b0.z;
        acc[3] += xv.x * a0.w + xv.y * b0.w;
        acc[4] += xv.x * a1.x + xv.y * b1.x;
        acc[5] += xv.x * a1.y + xv.y * b1.y;
        acc[6] += xv.x * a1.z + xv.y * b1.z;
        acc[7] += xv.x * a1.w + xv.y * b1.w;
    }
#pragma unroll
    for (int e = 0; e < NE; e++) {
#pragma unroll
        for (int s = 16; s > 0; s >>= 1)
            acc[e] += __shfl_xor_sync(0xFFFFFFFFu, acc[e], s);
    }
    if (lane == 0) {
        float v[NE];
#pragma unroll
        for (int e = 0; e < NE; e++) v[e] = fmaxf(acc[e], 0.f);
        int e0 = 0; float p0 = v[0];
        int e1 = -1; float p1 = -1.f;
#pragma unroll
        for (int e = 1; e < NE; e++) {
            if (v[e] > p0)      { p1 = p0; e1 = e0; p0 = v[e]; e0 = e; }
            else if (v[e] > p1) { p1 = v[e]; e1 = e; }
        }
        float w0 = 1.f / (1.f + expf(p1 - p0));
        g_sel[2*n] = e0; g_sel[2*n+1] = e1;
        g_w[2*n] = w0;   g_w[2*n+1] = 1.f - w0;
    }
}

// ---------------- plan: scan-based ranking, conflict-free LDS ----------------
__global__ void plan_kernel() {
    __shared__ int cnt_s[NE][1024];
    __shared__ int off_s[NE], tot_s[NE];
    const int tid = threadIdx.x;
    const int wid = tid >> 5, lane = tid & 31;

    int sel8[8];
    int c[NE];
#pragma unroll
    for (int e = 0; e < NE; e++) c[e] = 0;
#pragma unroll
    for (int j = 0; j < 8; j++) {
        sel8[j] = g_sel[tid * 8 + j];
        c[sel8[j]]++;
    }
#pragma unroll
    for (int e = 0; e < NE; e++) cnt_s[e][tid] = c[e];
    __syncthreads();

    // warp wid scans expert wid; lane reads threads {lane + 32j} -> bank = lane (conflict-free)
    if (wid < NE) {
        int v[32];
        int s = 0;
#pragma unroll
        for (int j = 0; j < 32; j++) { v[j] = cnt_s[wid][lane + 32 * j]; s += v[j]; }
        int incl = s;
#pragma unroll
        for (int d = 1; d < 32; d <<= 1) {
            int t = __shfl_up_sync(0xFFFFFFFFu, incl, d);
            if (lane >= d) incl += t;
        }
        int run = incl - s;
        if (lane == 31) tot_s[wid] = incl;
#pragma unroll
        for (int j = 0; j < 32; j++) { cnt_s[wid][lane + 32 * j] = run; run += v[j]; }
    }
    __syncthreads();
    if (tid == 0) {
        int o = 0;
        for (int e = 0; e < NE; e++) {
            off_s[e] = o; g_off[e] = o; g_cnt[e] = tot_s[e]; o += tot_s[e];
        }
    }
    __syncthreads();

    int pref[NE];
#pragma unroll
    for (int e = 0; e < NE; e++) pref[e] = off_s[e] + cnt_s[e][tid];
#pragma unroll
    for (int j = 0; j < 8; j++) {
        int i = tid * 8 + j;
        int e = sel8[j];
        int r = pref[e]++;
        g_perm[r]   = i >> 1;
        g_wgt[r]    = g_w[i];
        g_rowpos[i] = r;
    }
}

// ---------------- weight converts ----------------
__global__ void convert1_kernel(const float4* __restrict__ src) {
    const int n4 = NE * DIMD * HID / 4;
    __half2* dst = (__half2*)g_w1h;
    for (int i = blockIdx.x * blockDim.x + threadIdx.x; i < n4; i += gridDim.x * blockDim.x) {
        float4 v = src[i];
        dst[2*i]   = __floats2half2_rn(v.x, v.y);
        dst[2*i+1] = __floats2half2_rn(v.z, v.w);
    }
}
// conv2: 64-thread blocks (tiny footprint -> co-residency beside workers), flag on completion
__global__ void convert2_kernel(const float4* __restrict__ src) {
    const int n4 = NE * HID * OUTD / 4;
    __half2* dst = (__half2*)g_w2h;
    for (int i = blockIdx.x * 64 + threadIdx.x; i < n4; i += gridDim.x * 64) {
        float4 v = src[i];
        dst[2*i]   = __floats2half2_rn(v.x, v.y);
        dst[2*i+1] = __floats2half2_rn(v.z, v.w);
    }
    __threadfence();
    __syncthreads();
    if (threadIdx.x == 0) atomicAdd(&g_w2ready, 1);
}

// ---------------- GEMM tile as device function ----------------
template<int KD, int ND, bool FIRST>
__device__ __forceinline__ void gemm_tile(char* smem, uint32_t sb,
                                          int e, int row0, int col0,
                                          const float* __restrict__ biasBase)
{
    const int cnt  = g_cnt[e];
    const int base = g_off[e];

    const __half* Asrc = FIRST ? g_xh : g_hh;
    const __half* B    = (FIRST ? g_w1h : g_w2h) + (size_t)e * KD * ND + col0;
    const float*  bias = biasBase + (size_t)e * ND + col0;

    const int tid = threadIdx.x;
    const int wid = tid >> 5, lane = tid & 31;
    const int wm = wid >> 2, wn = wid & 3;
    const int lq = lane >> 2, lr = lane & 3;
    const int ls = lane & 7;

    int aoff[4];
#pragma unroll
    for (int i = 0; i < 4; i++) {
        int r  = (tid >> 3) + 32 * i;
        int gr = row0 + r;
        int cr = (gr < cnt) ? gr : 0;
        aoff[i] = (FIRST ? g_perm[base + cr] : (base + cr)) * KD;
    }
    const int aj = tid & 7;
    const int bc = tid & 31;
    const int bkl = tid >> 5;

    auto fill = [&](int kt) {
        char* st = smem + (size_t)(kt & 3) * STAGE;
#pragma unroll
        for (int i = 0; i < 4; i++) {
            int r = (tid >> 3) + 32 * i;
            cp16(st + SW128(r * 128 + aj * 16), Asrc + aoff[i] + kt * 64 + aj * 8);
        }
#pragma unroll
        for (int i = 0; i < 8; i++) {
            int k = bkl + 8 * i;
            cp16(st + 16384 + k * 512 + ((bc ^ bkl) << 4),
                 B + (size_t)(kt * 64 + k) * ND + bc * 8);
        }
        asm volatile("cp.async.commit_group;");
    };

    const int KT = KD / 64;
    fill(0); fill(1); fill(2);

    float acc[4][8][4];
#pragma unroll
    for (int f = 0; f < 4; f++)
#pragma unroll
        for (int g = 0; g < 8; g++)
#pragma unroll
            for (int q = 0; q < 4; q++) acc[f][g][q] = 0.f;

    const uint32_t aRowB = (uint32_t)(wm * 64 + ((lane >> 3) & 1) * 8 + ls) * 128;
    const uint32_t aCh   = (uint32_t)(lane >> 4);
    const uint32_t bRowB = (uint32_t)(((lane >> 3) & 1) * 8 + ls) * 512;
    const uint32_t bC0   = (uint32_t)(wn * 8 + (lane >> 4));

#pragma unroll 1
    for (int kt = 0; kt < KT; kt++) {
        const int rem = KT - 1 - kt;
        if (rem >= 2)      asm volatile("cp.async.wait_group 2;");
        else if (rem == 1) asm volatile("cp.async.wait_group 1;");
        else               asm volatile("cp.async.wait_group 0;");
        __syncthreads();
        if (kt + 3 < KT) fill(kt + 3);

        const uint32_t sA = sb + (uint32_t)(kt & 3) * STAGE;
        const uint32_t sB = sA + 16384;
#pragma unroll
        for (int ks = 0; ks < 4; ks++) {
            uint32_t a[4][4], b[4][4];
#pragma unroll
            for (int f = 0; f < 4; f++)
                ldm4(a[f], sA + aRowB + f * 2048 + (((2 * ks + aCh) ^ ls) << 4));
#pragma unroll
            for (int p = 0; p < 4; p++)
                ldm4t(b[p], sB + ks * 8192 + bRowB + (((bC0 + 2 * p) ^ ls) << 4));
#pragma unroll
            for (int f = 0; f < 4; f++)
#pragma unroll
                for (int g = 0; g < 8; g++)
                    mma16816(acc[f][g], a[f], &b[g >> 1][(g & 1) * 2]);
        }
    }

#pragma unroll
    for (int f = 0; f < 4; f++) {
        const int r0 = row0 + wm * 64 + f * 16 + lq;
        const int r1 = r0 + 8;
#pragma unroll
        for (int g = 0; g < 8; g++) {
            const int col = wn * 64 + g * 8 + 2 * lr;
            float2 bb = *(const float2*)(bias + col);
            float v00 = fmaxf(acc[f][g][0] + bb.x, 0.f);
            float v01 = fmaxf(acc[f][g][1] + bb.y, 0.f);
            float v10 = fmaxf(acc[f][g][2] + bb.x, 0.f);
            float v11 = fmaxf(acc[f][g][3] + bb.y, 0.f);
            if (FIRST) {
                if (r0 < cnt)
                    *(__half2*)(g_hh + (size_t)(base + r0) * ND + col0 + col) = __floats2half2_rn(v00, v01);
                if (r1 < cnt)
                    *(__half2*)(g_hh + (size_t)(base + r1) * ND + col0 + col) = __floats2half2_rn(v10, v11);
            } else {
                if (r0 < cnt)
                    *(float2*)(g_ybuf + (size_t)(base + r0) * ND + col0 + col) = make_float2(v00, v01);
                if (r1 < cnt)
                    *(float2*)(g_ybuf + (size_t)(base + r1) * ND + col0 + col) = make_float2(v10, v11);
            }
        }
    }
}

// ---------------- persistent worker: queue = [G1 items][G2 items] ----------------
__global__ __launch_bounds__(256, 1)
void worker_kernel(const float* __restrict__ b1, const float* __restrict__ b2)
{
    extern __shared__ __align__(128) char smem[];
    __shared__ int s_item;
    const uint32_t sb = smem_u32(smem);

    for (;;) {
        __syncthreads();
        if (threadIdx.x == 0) s_item = atomicAdd(&g_qhead, 1);
        __syncthreads();
        const int i = s_item;
        if (i >= NTOT) return;

        if (i < NG1) {
            const int e  = i / (NRT * 16);
            const int r  = i % (NRT * 16);
            const int ct = r / NRT;
            const int rt = r % NRT;
            if (rt * 128 < g_cnt[e])
                gemm_tile<DIMD, HID, true>(smem, sb, e, rt * 128, ct * 256, b1);
            __threadfence();
            __syncthreads();
            if (threadIdx.x == 0) atomicAdd(&g_done1[e], 1);
        } else {
            const int j  = i - NG1;
            const int e  = j / (NRT * 4);
            const int r  = j % (NRT * 4);
            const int ct = r / NRT;
            const int rt = r % NRT;
            if (threadIdx.x == 0) {
                while (atomicAdd(&g_done1[e], 0) < NRT * 16) __nanosleep(128);
                while (atomicAdd(&g_w2ready, 0) < CONV2_BLOCKS) __nanosleep(128);
            }
            __syncthreads();
            if (rt * 128 < g_cnt[e])
                gemm_tile<HID, OUTD, false>(smem, sb, e, rt * 128, ct * 256, b2);
        }
    }
}

// ---------------- combine ----------------
__global__ void combine_kernel(float* __restrict__ out) {
    int gid = blockIdx.x * blockDim.x + threadIdx.x;
    if (gid >= N_TOK * OUTD / 4) return;
    int n = gid / (OUTD / 4);
    int c = (gid % (OUTD / 4)) * 4;
    int r0 = g_rowpos[2*n], r1 = g_rowpos[2*n + 1];
    float w0 = g_wgt[r0], w1 = g_wgt[r1];
    float4 y0 = *(const float4*)(g_ybuf + (size_t)r0 * OUTD + c);
    float4 y1 = *(const float4*)(g_ybuf + (size_t)r1 * OUTD + c);
    float4 o;
    o.x = w0*y0.x + w1*y1.x;
    o.y = w0*y0.y + w1*y1.y;
    o.z = w0*y0.z + w1*y1.z;
    o.w = w0*y0.w + w1*y1.w;
    *(float4*)(out + (size_t)n * OUTD + c) = o;
}

// ---------------- launch ----------------
extern "C" void kernel_launch(void* const* d_in, const int* in_sizes, int n_in,
                              void* d_out, int out_size) {
    const float* x  = (const float*)d_in[0];
    const float* Wg = (const float*)d_in[1];
    const float* W1 = (const float*)d_in[2];
    const float* b1 = (const float*)d_in[3];
    const float* W2 = (const float*)d_in[4];
    const float* b2 = (const float*)d_in[5];
    float* out = (float*)d_out;

    static cudaStream_t s1 = nullptr;
    static cudaEvent_t evFork = nullptr, evC1 = nullptr, evC2 = nullptr;
    static bool inited = false;
    if (!inited) {
        cudaStreamCreateWithFlags(&s1, cudaStreamNonBlocking);
        cudaEventCreateWithFlags(&evFork, cudaEventDisableTiming);
        cudaEventCreateWithFlags(&evC1,  cudaEventDisableTiming);
        cudaEventCreateWithFlags(&evC2,  cudaEventDisableTiming);
        cudaFuncSetAttribute(worker_kernel,
                             cudaFuncAttributeMaxDynamicSharedMemorySize, SMEM_TOTAL);
        inited = true;
    }

    // reset device flags, then fork converts to side stream
    flags_init_kernel<<<1, 32>>>();
    cudaEventRecord(evFork, 0);
    cudaStreamWaitEvent(s1, evFork, 0);
    convert1_kernel<<<4096, 256, 0, s1>>>((const float4*)W1);
    cudaEventRecord(evC1, s1);
    convert2_kernel<<<CONV2_BLOCKS, 64, 0, s1>>>((const float4*)W2);
    cudaEventRecord(evC2, s1);

    // main: fused gate+convert, plan
    gate_kernel<<<N_TOK / 8, 256>>>(x, Wg);
    plan_kernel<<<1, 1024>>>();

    // persistent fused G1+G2 (needs w1h -> wait conv1; conv2 gated by device flag inside)
    cudaStreamWaitEvent(0, evC1, 0);
    worker_kernel<<<256, 256, SMEM_TOTAL>>>(b1, b2);

    // join side stream before the final kernel (capture requires the fork to rejoin;
    // conv2 finished long before the worker, so this adds no serialization)
    cudaStreamWaitEvent(0, evC2, 0);
    combine_kernel<<<(N_TOK * OUTD / 4 + 255) / 256, 256>>>(out);
}